// round 3
// baseline (speedup 1.0000x reference)
#include <cuda_runtime.h>
#include <cuda_bf16.h>
#include <cstdint>

#define DEVINL __device__ __forceinline__

static constexpr int MDIM = 8192;
static constexpr int NDIM = 8192;
static constexpr int KDIM = 64;
static constexpr int TILE_M = 128;
static constexpr int TILE_N = 128;

// Dynamic SMEM layout (bf16 tiles, XOR-swizzled)
// A tiles: [128 rows][64 k] bf16, 128 B/row.  B tiles: [64 k][128 n] bf16, 256 B/row.
static constexpr int SM_A_HI = 0;
static constexpr int SM_A_LO = SM_A_HI + TILE_M * KDIM * 2;   // +16 KB
static constexpr int SM_B_HI = SM_A_LO + TILE_M * KDIM * 2;   // +16 KB
static constexpr int SM_B_LO = SM_B_HI + KDIM * TILE_N * 2;   // +16 KB
static constexpr int SM_TOTAL = SM_B_LO + KDIM * TILE_N * 2;  // 64 KB

DEVINL uint32_t smem_u32(const void* p) {
    uint32_t a;
    asm("{ .reg .u64 t; cvta.to.shared.u64 t, %1; cvt.u32.u64 %0, t; }" : "=r"(a) : "l"(p));
    return a;
}

DEVINL void ldmA(uint32_t* r, uint32_t addr) {
    asm volatile("ldmatrix.sync.aligned.m8n8.x4.shared.b16 {%0,%1,%2,%3}, [%4];"
                 : "=r"(r[0]), "=r"(r[1]), "=r"(r[2]), "=r"(r[3]) : "r"(addr));
}

DEVINL void ldmBT(uint32_t* r, uint32_t addr) {
    asm volatile("ldmatrix.sync.aligned.m8n8.x4.trans.shared.b16 {%0,%1,%2,%3}, [%4];"
                 : "=r"(r[0]), "=r"(r[1]), "=r"(r[2]), "=r"(r[3]) : "r"(addr));
}

DEVINL void mma_bf16(float* c, const uint32_t* a, const uint32_t* b) {
    asm volatile(
        "mma.sync.aligned.m16n8k16.row.col.f32.bf16.bf16.f32 "
        "{%0,%1,%2,%3}, {%4,%5,%6,%7}, {%8,%9}, {%0,%1,%2,%3};"
        : "+f"(c[0]), "+f"(c[1]), "+f"(c[2]), "+f"(c[3])
        : "r"(a[0]), "r"(a[1]), "r"(a[2]), "r"(a[3]), "r"(b[0]), "r"(b[1]));
}

DEVINL uint32_t pack_hi2(float a, float b, uint32_t& lo_out) {
    __nv_bfloat16 ha = __float2bfloat16(a);
    __nv_bfloat16 hb = __float2bfloat16(b);
    __nv_bfloat16 la = __float2bfloat16(a - __bfloat162float(ha));
    __nv_bfloat16 lb = __float2bfloat16(b - __bfloat162float(hb));
    __nv_bfloat162 h; h.x = ha; h.y = hb;
    __nv_bfloat162 l; l.x = la; l.y = lb;
    lo_out = *reinterpret_cast<uint32_t*>(&l);
    return *reinterpret_cast<uint32_t*>(&h);
}

__global__ void __launch_bounds__(256, 2)
sddmm_kernel(const float* __restrict__ x, const float* __restrict__ y,
             const float* __restrict__ z, float* __restrict__ out) {
    extern __shared__ char smem[];
    const uint32_t sbase = smem_u32(smem);
    const int tid = threadIdx.x;
    const int lane = tid & 31;
    const int wid = tid >> 5;
    const int m0 = blockIdx.y * TILE_M;
    const int n0 = blockIdx.x * TILE_N;

    // ---- Stage y tile [128 x 64] -> A_hi/A_lo bf16, swizzled 128 B rows ----
    // 2048 float4 total, 8 per thread. idx -> (row = idx>>4, k4 = idx&15).
    #pragma unroll
    for (int it = 0; it < 8; ++it) {
        const int idx = tid + it * 256;
        const int row = idx >> 4;
        const int k4 = idx & 15;
        float4 v = *reinterpret_cast<const float4*>(y + (size_t)(m0 + row) * KDIM + k4 * 4);
        uint32_t l01, l23;
        uint32_t h01 = pack_hi2(v.x, v.y, l01);
        uint32_t h23 = pack_hi2(v.z, v.w, l23);
        uint32_t off = (uint32_t)row * 128u + (((uint32_t)k4 * 8u) ^ (((uint32_t)row & 7u) << 4));
        *reinterpret_cast<uint2*>(smem + SM_A_HI + off) = make_uint2(h01, h23);
        *reinterpret_cast<uint2*>(smem + SM_A_LO + off) = make_uint2(l01, l23);
    }

    // ---- Stage z tile [64 x 128] -> B_hi/B_lo bf16, swizzled 256 B rows ----
    // 2048 float4 total. idx -> (k = idx>>5, n4 = idx&31).
    #pragma unroll
    for (int it = 0; it < 8; ++it) {
        const int idx = tid + it * 256;
        const int k = idx >> 5;
        const int n4 = idx & 31;
        float4 v = *reinterpret_cast<const float4*>(z + (size_t)k * NDIM + n0 + n4 * 4);
        uint32_t l01, l23;
        uint32_t h01 = pack_hi2(v.x, v.y, l01);
        uint32_t h23 = pack_hi2(v.z, v.w, l23);
        uint32_t off = (uint32_t)k * 256u + (((uint32_t)n4 * 8u) ^ (((uint32_t)k & 7u) << 4));
        *reinterpret_cast<uint2*>(smem + SM_B_HI + off) = make_uint2(h01, h23);
        *reinterpret_cast<uint2*>(smem + SM_B_LO + off) = make_uint2(l01, l23);
    }

    __syncthreads();

    // ---- Warp tiling: 4 (M) x 2 (N); each warp: 32 rows x 64 cols ----
    const int wm = wid >> 1;   // 0..3
    const int wn = wid & 1;    // 0..1

    // ldmatrix lane patterns
    const int m_off = ((lane >> 3) & 1) * 8 + (lane & 7);
    const int koct = lane >> 4;                 // A: k-octet select
    const int k_off = m_off;                    // B: same pattern for k rows
    const int noct = lane >> 4;                 // B: n-octet select
    const uint32_t xr = ((uint32_t)(lane & 7)) << 4;

    // Per-lane fixed pieces
    const uint32_t a_row0 = (uint32_t)(wm * 32 + m_off) * 128u;        // mt=0
    const uint32_t a_row1 = a_row0 + 16u * 128u;                       // mt=1
    uint32_t b_ncol[4];
    #pragma unroll
    for (int j = 0; j < 4; ++j)
        b_ncol[j] = (((uint32_t)(wn * 64 + j * 16 + noct * 8) * 2u) ^ xr);
    const uint32_t b_krow = (uint32_t)k_off * 256u;

    float acc[2][8][4];
    #pragma unroll
    for (int mt = 0; mt < 2; ++mt)
        #pragma unroll
        for (int nt = 0; nt < 8; ++nt)
            #pragma unroll
            for (int e = 0; e < 4; ++e) acc[mt][nt][e] = 0.0f;

    const uint32_t aBase[3] = { sbase + SM_A_HI, sbase + SM_A_HI, sbase + SM_A_LO };
    const uint32_t bBase[3] = { sbase + SM_B_HI, sbase + SM_B_LO, sbase + SM_B_HI };

    #pragma unroll
    for (int pass = 0; pass < 3; ++pass) {
        const uint32_t ab = aBase[pass];
        const uint32_t bb = bBase[pass];
        #pragma unroll
        for (int ks = 0; ks < 4; ++ks) {
            const uint32_t akoff = (((uint32_t)(ks * 32 + koct * 16)) ^ xr);
            uint32_t aF[2][4];
            ldmA(aF[0], ab + a_row0 + akoff);
            ldmA(aF[1], ab + a_row1 + akoff);

            uint32_t bF[4][4];
            const uint32_t brow = (uint32_t)(ks * 16) * 256u + b_krow;
            #pragma unroll
            for (int j = 0; j < 4; ++j)
                ldmBT(bF[j], bb + brow + b_ncol[j]);

            #pragma unroll
            for (int mt = 0; mt < 2; ++mt)
                #pragma unroll
                for (int j = 0; j < 4; ++j) {
                    mma_bf16(acc[mt][2 * j + 0], aF[mt], &bF[j][0]);
                    mma_bf16(acc[mt][2 * j + 1], aF[mt], &bF[j][2]);
                }
        }
    }

    // ---- Epilogue: out = x * acc, direct from registers ----
    // c-frag: (c0,c1) at (row=grp, col=2q), (c2,c3) at (row=grp+8, col=2q)
    const int grp = lane >> 2;
    const int q = lane & 3;
    const int row_base = m0 + wm * 32 + grp;
    const int col_base = n0 + wn * 64 + 2 * q;

    #pragma unroll
    for (int nt = 0; nt < 8; ++nt) {
        const int col = col_base + nt * 8;
        #pragma unroll
        for (int mt = 0; mt < 2; ++mt) {
            const size_t r0 = (size_t)(row_base + mt * 16) * NDIM + col;
            const size_t r1 = r0 + 8 * NDIM;
            float2 x0 = *reinterpret_cast<const float2*>(x + r0);
            float2 x1 = *reinterpret_cast<const float2*>(x + r1);
            float2 o0, o1;
            o0.x = x0.x * acc[mt][nt][0];
            o0.y = x0.y * acc[mt][nt][1];
            o1.x = x1.x * acc[mt][nt][2];
            o1.y = x1.y * acc[mt][nt][3];
            *reinterpret_cast<float2*>(out + r0) = o0;
            *reinterpret_cast<float2*>(out + r1) = o1;
        }
    }
}

extern "C" void kernel_launch(void* const* d_in, const int* in_sizes, int n_in,
                              void* d_out, int out_size) {
    const float* x = (const float*)d_in[0];
    const float* y = (const float*)d_in[1];
    const float* z = (const float*)d_in[2];
    float* out = (float*)d_out;

    cudaFuncSetAttribute(sddmm_kernel, cudaFuncAttributeMaxDynamicSharedMemorySize, SM_TOTAL);
    dim3 grid(NDIM / TILE_N, MDIM / TILE_M);  // (64, 64)
    sddmm_kernel<<<grid, 256, SM_TOTAL>>>(x, y, z, out);
}

// round 4
// speedup vs baseline: 1.0796x; 1.0796x over previous
#include <cuda_runtime.h>
#include <cuda_bf16.h>
#include <cstdint>

#define DEVINL __device__ __forceinline__

static constexpr int MDIM = 8192;
static constexpr int NDIM = 8192;
static constexpr int KDIM = 64;
static constexpr int TILE_M = 128;
static constexpr int TILE_N = 128;

// Dynamic SMEM layout (bf16 tiles, XOR-swizzled)
// A tiles: [128 rows][64 k] bf16, 128 B/row.  B tiles: [64 k][128 n] bf16, 256 B/row.
static constexpr int SM_A_HI = 0;
static constexpr int SM_A_LO = SM_A_HI + TILE_M * KDIM * 2;   // +16 KB
static constexpr int SM_B_HI = SM_A_LO + TILE_M * KDIM * 2;   // +16 KB
static constexpr int SM_B_LO = SM_B_HI + KDIM * TILE_N * 2;   // +16 KB
static constexpr int SM_TOTAL = SM_B_LO + KDIM * TILE_N * 2;  // 64 KB

DEVINL uint32_t smem_u32(const void* p) {
    uint32_t a;
    asm("{ .reg .u64 t; cvta.to.shared.u64 t, %1; cvt.u32.u64 %0, t; }" : "=r"(a) : "l"(p));
    return a;
}

DEVINL void ldmA(uint32_t* r, uint32_t addr) {
    asm volatile("ldmatrix.sync.aligned.m8n8.x4.shared.b16 {%0,%1,%2,%3}, [%4];"
                 : "=r"(r[0]), "=r"(r[1]), "=r"(r[2]), "=r"(r[3]) : "r"(addr));
}

DEVINL void ldmBT(uint32_t* r, uint32_t addr) {
    asm volatile("ldmatrix.sync.aligned.m8n8.x4.trans.shared.b16 {%0,%1,%2,%3}, [%4];"
                 : "=r"(r[0]), "=r"(r[1]), "=r"(r[2]), "=r"(r[3]) : "r"(addr));
}

DEVINL void mma_bf16(float* c, const uint32_t* a, const uint32_t* b) {
    asm volatile(
        "mma.sync.aligned.m16n8k16.row.col.f32.bf16.bf16.f32 "
        "{%0,%1,%2,%3}, {%4,%5,%6,%7}, {%8,%9}, {%0,%1,%2,%3};"
        : "+f"(c[0]), "+f"(c[1]), "+f"(c[2]), "+f"(c[3])
        : "r"(a[0]), "r"(a[1]), "r"(a[2]), "r"(a[3]), "r"(b[0]), "r"(b[1]));
}

DEVINL uint32_t pack_hi2(float a, float b, uint32_t& lo_out) {
    __nv_bfloat16 ha = __float2bfloat16(a);
    __nv_bfloat16 hb = __float2bfloat16(b);
    __nv_bfloat16 la = __float2bfloat16(a - __bfloat162float(ha));
    __nv_bfloat16 lb = __float2bfloat16(b - __bfloat162float(hb));
    __nv_bfloat162 h; h.x = ha; h.y = hb;
    __nv_bfloat162 l; l.x = la; l.y = lb;
    lo_out = *reinterpret_cast<uint32_t*>(&l);
    return *reinterpret_cast<uint32_t*>(&h);
}

__global__ void __launch_bounds__(256, 2)
sddmm_kernel(const float* __restrict__ x, const float* __restrict__ y,
             const float* __restrict__ z, float* __restrict__ out) {
    extern __shared__ char smem[];
    const uint32_t sbase = smem_u32(smem);
    const int tid = threadIdx.x;
    const int lane = tid & 31;
    const int wid = tid >> 5;
    const int m0 = blockIdx.y * TILE_M;
    const int n0 = blockIdx.x * TILE_N;

    // ---- Stage y tile [128 x 64] -> A_hi/A_lo bf16, swizzled 128 B rows ----
    #pragma unroll
    for (int it = 0; it < 8; ++it) {
        const int idx = tid + it * 256;
        const int row = idx >> 4;
        const int k4 = idx & 15;
        float4 v = *reinterpret_cast<const float4*>(y + (size_t)(m0 + row) * KDIM + k4 * 4);
        uint32_t l01, l23;
        uint32_t h01 = pack_hi2(v.x, v.y, l01);
        uint32_t h23 = pack_hi2(v.z, v.w, l23);
        uint32_t off = (uint32_t)row * 128u + (((uint32_t)k4 * 8u) ^ (((uint32_t)row & 7u) << 4));
        *reinterpret_cast<uint2*>(smem + SM_A_HI + off) = make_uint2(h01, h23);
        *reinterpret_cast<uint2*>(smem + SM_A_LO + off) = make_uint2(l01, l23);
    }

    // ---- Stage z tile [64 x 128] -> B_hi/B_lo bf16, swizzled 256 B rows ----
    #pragma unroll
    for (int it = 0; it < 8; ++it) {
        const int idx = tid + it * 256;
        const int k = idx >> 5;
        const int n4 = idx & 31;
        float4 v = *reinterpret_cast<const float4*>(z + (size_t)k * NDIM + n0 + n4 * 4);
        uint32_t l01, l23;
        uint32_t h01 = pack_hi2(v.x, v.y, l01);
        uint32_t h23 = pack_hi2(v.z, v.w, l23);
        uint32_t off = (uint32_t)k * 256u + (((uint32_t)n4 * 8u) ^ (((uint32_t)k & 7u) << 4));
        *reinterpret_cast<uint2*>(smem + SM_B_HI + off) = make_uint2(h01, h23);
        *reinterpret_cast<uint2*>(smem + SM_B_LO + off) = make_uint2(l01, l23);
    }

    __syncthreads();

    // ---- Warp tiling: 4 (M) x 2 (N); each warp: 32 rows x 64 cols ----
    const int wm = wid >> 1;   // 0..3
    const int wn = wid & 1;    // 0..1

    // ldmatrix lane patterns
    const int m_off = ((lane >> 3) & 1) * 8 + (lane & 7);
    const int koct = lane >> 4;                 // A: k-octet select
    const int k_off = m_off;                    // B: k-row pattern
    const int noct = lane >> 4;                 // B: n-octet select
    const uint32_t xr = ((uint32_t)(lane & 7)) << 4;

    const uint32_t a_row0 = (uint32_t)(wm * 32 + m_off) * 128u;  // mt=0
    const uint32_t a_row1 = a_row0 + 16u * 128u;                 // mt=1
    uint32_t b_ncol[4];
    #pragma unroll
    for (int j = 0; j < 4; ++j)
        b_ncol[j] = (((uint32_t)(wn * 64 + j * 16 + noct * 8) * 2u) ^ xr);
    const uint32_t b_krow = (uint32_t)k_off * 256u;

    float acc[2][8][4];
    #pragma unroll
    for (int mt = 0; mt < 2; ++mt)
        #pragma unroll
        for (int nt = 0; nt < 8; ++nt)
            #pragma unroll
            for (int e = 0; e < 4; ++e) acc[mt][nt][e] = 0.0f;

    const uint32_t aHb = sbase + SM_A_HI;
    const uint32_t aLb = sbase + SM_A_LO;
    const uint32_t bHb = sbase + SM_B_HI;
    const uint32_t bLb = sbase + SM_B_LO;

    // ---- Mainloop: fragments loaded ONCE per k-step, reused across passes ----
    // D = Ahi*Bhi + Alo*Bhi + Ahi*Blo (fp32 accum)
    #pragma unroll
    for (int ks = 0; ks < 4; ++ks) {
        const uint32_t akoff = (((uint32_t)(ks * 32 + koct * 16)) ^ xr);
        const uint32_t brow = (uint32_t)(ks * 16) * 256u + b_krow;

        uint32_t aH[2][4], aL[2][4];
        ldmA(aH[0], aHb + a_row0 + akoff);
        ldmA(aH[1], aHb + a_row1 + akoff);
        ldmA(aL[0], aLb + a_row0 + akoff);
        ldmA(aL[1], aLb + a_row1 + akoff);

        uint32_t bF[4][4];
        #pragma unroll
        for (int j = 0; j < 4; ++j)
            ldmBT(bF[j], bHb + brow + b_ncol[j]);

        // hi*hi and lo*hi against bH
        #pragma unroll
        for (int mt = 0; mt < 2; ++mt)
            #pragma unroll
            for (int j = 0; j < 4; ++j) {
                mma_bf16(acc[mt][2 * j + 0], aH[mt], &bF[j][0]);
                mma_bf16(acc[mt][2 * j + 1], aH[mt], &bF[j][2]);
            }
        #pragma unroll
        for (int mt = 0; mt < 2; ++mt)
            #pragma unroll
            for (int j = 0; j < 4; ++j) {
                mma_bf16(acc[mt][2 * j + 0], aL[mt], &bF[j][0]);
                mma_bf16(acc[mt][2 * j + 1], aL[mt], &bF[j][2]);
            }

        // reload bF <- B_lo, then hi*lo
        #pragma unroll
        for (int j = 0; j < 4; ++j)
            ldmBT(bF[j], bLb + brow + b_ncol[j]);
        #pragma unroll
        for (int mt = 0; mt < 2; ++mt)
            #pragma unroll
            for (int j = 0; j < 4; ++j) {
                mma_bf16(acc[mt][2 * j + 0], aH[mt], &bF[j][0]);
                mma_bf16(acc[mt][2 * j + 1], aH[mt], &bF[j][2]);
            }
    }

    // ---- Epilogue: out = x * acc, direct from registers ----
    const int grp = lane >> 2;
    const int q = lane & 3;
    const int row_base = m0 + wm * 32 + grp;
    const int col_base = n0 + wn * 64 + 2 * q;

    #pragma unroll
    for (int nt = 0; nt < 8; ++nt) {
        const int col = col_base + nt * 8;
        #pragma unroll
        for (int mt = 0; mt < 2; ++mt) {
            const size_t r0 = (size_t)(row_base + mt * 16) * NDIM + col;
            const size_t r1 = r0 + 8 * NDIM;
            float2 x0 = *reinterpret_cast<const float2*>(x + r0);
            float2 x1 = *reinterpret_cast<const float2*>(x + r1);
            float2 o0, o1;
            o0.x = x0.x * acc[mt][nt][0];
            o0.y = x0.y * acc[mt][nt][1];
            o1.x = x1.x * acc[mt][nt][2];
            o1.y = x1.y * acc[mt][nt][3];
            *reinterpret_cast<float2*>(out + r0) = o0;
            *reinterpret_cast<float2*>(out + r1) = o1;
        }
    }
}

extern "C" void kernel_launch(void* const* d_in, const int* in_sizes, int n_in,
                              void* d_out, int out_size) {
    const float* x = (const float*)d_in[0];
    const float* y = (const float*)d_in[1];
    const float* z = (const float*)d_in[2];
    float* out = (float*)d_out;

    cudaFuncSetAttribute(sddmm_kernel, cudaFuncAttributeMaxDynamicSharedMemorySize, SM_TOTAL);
    dim3 grid(NDIM / TILE_N, MDIM / TILE_M);  // (64, 64)
    sddmm_kernel<<<grid, 256, SM_TOTAL>>>(x, y, z, out);
}